// round 14
// baseline (speedup 1.0000x reference)
#include <cuda_runtime.h>
#include <cuda_fp16.h>
#include <mma.h>

using namespace nvcuda;

#define NROWS 65536      // B*T = 8*8192
#define DIN   1024
#define DADDR 64
#define NEXP  12
#define KSEL  3

// k_gemm geometry: BK=32, padded row 40 halves (80B), 4-stage ring, paired iters
#define BKH   40
#define STG_HALVES (2 * 128 * BKH)       // A+B per stage = 10240 halves
#define NSTG  4
#define SMEM_DYN (NSTG * STG_HALVES * 2) // 81920 B -> 2 CTAs/SM

// epilogue strip: 16 rows x 68 floats per warp (ldm 68 = 272B, 16B-multiple)
#define EPLD  68

// k_xa2 geometry: BK=32, padded row 40 halves
#define XBK   40

// ---------------- static device scratch (no allocations) ----------------
__device__ __half g_xh [NROWS * DIN];
__device__ __half g_hh [NROWS * DIN];
__device__ __half g_w1h[NEXP * DIN * DIN];
__device__ __half g_w2h[NEXP * DIN * DIN];
__device__ __half g_sloth[(size_t)KSEL * NROWS * DIN];
__device__ float  g_xa [NROWS * DADDR];
__device__ int    g_cnt1[NEXP], g_cnt2[NEXP];
__device__ int    g_off1[NEXP], g_off2[NEXP];
__device__ int    g_rows1[NEXP * NROWS];
__device__ float  g_wts1 [NEXP * NROWS];
__device__ int    g_rows2[NEXP * NROWS];
__device__ float  g_wts2 [NEXP * NROWS];
__device__ int    g_pos1[NROWS * 3];
__device__ int    g_pos2[NROWS * 3];
__device__ int    g_r3e[NROWS * 3];
__device__ float  g_r3w[NROWS * 3];

// ---------------- helpers ----------------
__device__ __forceinline__ uint4 pack8h(float4 a, float4 b) {
    union { __half2 h2[4]; uint4 u; } p;
    p.h2[0] = __floats2half2_rn(a.x, a.y);
    p.h2[1] = __floats2half2_rn(a.z, a.w);
    p.h2[2] = __floats2half2_rn(b.x, b.y);
    p.h2[3] = __floats2half2_rn(b.z, b.w);
    return p.u;
}
__device__ __forceinline__ float gelu_exact(float v) {
    return 0.5f * v * (1.f + erff(v * 0.70710678118654752f));
}

#define CP16(dst_s32, src, sz) \
    asm volatile("cp.async.cg.shared.global [%0], [%1], 16, %2;\n" \
                 :: "r"(dst_s32), "l"(src), "r"(sz))
#define CP16F(dst_s32, src) \
    asm volatile("cp.async.cg.shared.global [%0], [%1], 16;\n" \
                 :: "r"(dst_s32), "l"(src))
#define CP_COMMIT() asm volatile("cp.async.commit_group;\n" ::)
#define CP_WAIT2()  asm volatile("cp.async.wait_group 2;\n" ::)
#define CP_WAIT0()  asm volatile("cp.async.wait_group 0;\n" ::)

// ---------------- tiny kernels ----------------
__global__ void k_zero_counts() {
    int t = threadIdx.x;
    if (t < NEXP) { g_cnt1[t] = 0; g_cnt2[t] = 0; }
}

__global__ void k_conv_w(const float* __restrict__ s, int which) {
    size_t i = ((size_t)blockIdx.x * blockDim.x + threadIdx.x) * 8;
    float4 a = *(const float4*)(s + i);
    float4 b = *(const float4*)(s + i + 4);
    __half* d = which ? g_w2h : g_w1h;
    *(uint4*)(d + i) = pack8h(a, b);
}

__global__ void k_prefix() {
    if (threadIdx.x == 0) {
        int s = 0;
        for (int e = 0; e < NEXP; e++) { g_off1[e] = s; s += g_cnt1[e]; }
        s = 0;
        for (int e = 0; e < NEXP; e++) { g_off2[e] = s; s += g_cnt2[e]; }
    }
}

// ---------------- routing stage A: split-fp16 tensor GEMM ----------------
// xa = x @ P_w^T via (x_hi + x_lo)(P_hi + P_lo)^T dropping lo*lo (err ~2^-22).
// Also writes g_xh = fp16(x) for GEMM pass 0 (x read exactly once).
__global__ __launch_bounds__(128) void k_xa2(const float* __restrict__ x,
                                             const float* __restrict__ P) {
    __shared__ __half Ah[128 * XBK], Al[128 * XBK];
    __shared__ __half Bh[DADDR * XBK], Bl[DADDR * XBK];
    int r0 = blockIdx.x * 128;
    int tid = threadIdx.x;
    int wid = tid >> 5;

    wmma::fragment<wmma::accumulator, 16, 16, 16, float> acc[2][4];
#pragma unroll
    for (int i = 0; i < 2; i++)
#pragma unroll
        for (int j = 0; j < 4; j++) wmma::fill_fragment(acc[i][j], 0.f);

#pragma unroll 1
    for (int k0 = 0; k0 < DIN; k0 += 32) {
        __syncthreads();
#pragma unroll
        for (int i = tid; i < 1024; i += 128) {
            int r = i >> 3, c4 = i & 7;
            float4 v = *(const float4*)(x + (size_t)(r0 + r) * DIN + k0 + c4 * 4);
            __half h0 = __float2half_rn(v.x), h1 = __float2half_rn(v.y);
            __half h2 = __float2half_rn(v.z), h3 = __float2half_rn(v.w);
            __half l0 = __float2half_rn(v.x - __half2float(h0));
            __half l1 = __float2half_rn(v.y - __half2float(h1));
            __half l2 = __float2half_rn(v.z - __half2float(h2));
            __half l3 = __float2half_rn(v.w - __half2float(h3));
            union { __half h[4]; uint2 u; } ph, pl;
            ph.h[0] = h0; ph.h[1] = h1; ph.h[2] = h2; ph.h[3] = h3;
            pl.h[0] = l0; pl.h[1] = l1; pl.h[2] = l2; pl.h[3] = l3;
            *(uint2*)(Ah + r * XBK + c4 * 4) = ph.u;
            *(uint2*)(Al + r * XBK + c4 * 4) = pl.u;
            *(uint2*)(g_xh + (size_t)(r0 + r) * DIN + k0 + c4 * 4) = ph.u;
        }
#pragma unroll
        for (int i = tid; i < 512; i += 128) {
            int a = i >> 3, c4 = i & 7;
            float4 v = *(const float4*)(P + (size_t)a * DIN + k0 + c4 * 4);
            __half h0 = __float2half_rn(v.x), h1 = __float2half_rn(v.y);
            __half h2 = __float2half_rn(v.z), h3 = __float2half_rn(v.w);
            __half l0 = __float2half_rn(v.x - __half2float(h0));
            __half l1 = __float2half_rn(v.y - __half2float(h1));
            __half l2 = __float2half_rn(v.z - __half2float(h2));
            __half l3 = __float2half_rn(v.w - __half2float(h3));
            union { __half h[4]; uint2 u; } ph, pl;
            ph.h[0] = h0; ph.h[1] = h1; ph.h[2] = h2; ph.h[3] = h3;
            pl.h[0] = l0; pl.h[1] = l1; pl.h[2] = l2; pl.h[3] = l3;
            *(uint2*)(Bh + a * XBK + c4 * 4) = ph.u;
            *(uint2*)(Bl + a * XBK + c4 * 4) = pl.u;
        }
        __syncthreads();
#pragma unroll
        for (int ks = 0; ks < 2; ks++) {
            wmma::fragment<wmma::matrix_a, 16, 16, 16, __half, wmma::row_major> afh[2], afl[2];
#pragma unroll
            for (int i = 0; i < 2; i++) {
                wmma::load_matrix_sync(afh[i], Ah + (wid * 32 + i * 16) * XBK + ks * 16, XBK);
                wmma::load_matrix_sync(afl[i], Al + (wid * 32 + i * 16) * XBK + ks * 16, XBK);
            }
#pragma unroll
            for (int j = 0; j < 4; j++) {
                wmma::fragment<wmma::matrix_b, 16, 16, 16, __half, wmma::col_major> bfh, bfl;
                wmma::load_matrix_sync(bfh, Bh + (j * 16) * XBK + ks * 16, XBK);
                wmma::load_matrix_sync(bfl, Bl + (j * 16) * XBK + ks * 16, XBK);
#pragma unroll
                for (int i = 0; i < 2; i++) {
                    wmma::mma_sync(acc[i][j], afh[i], bfh, acc[i][j]);
                    wmma::mma_sync(acc[i][j], afh[i], bfl, acc[i][j]);
                    wmma::mma_sync(acc[i][j], afl[i], bfh, acc[i][j]);
                }
            }
        }
    }
#pragma unroll
    for (int i = 0; i < 2; i++)
#pragma unroll
        for (int j = 0; j < 4; j++)
            wmma::store_matrix_sync(g_xa + (size_t)(r0 + wid * 32 + i * 16) * DADDR + j * 16,
                                    acc[i][j], DADDR, wmma::mem_row_major);
}

// ---------------- routing stage B: z, top-3, softmax, scatter ----------------
__global__ void k_route(const float* __restrict__ U1, const float* __restrict__ U2,
                        const float* __restrict__ U3) {
    int row = blockIdx.x * blockDim.x + threadIdx.x;
    float a[DADDR];
#pragma unroll
    for (int i = 0; i < DADDR; i += 4) {
        float4 v = *(const float4*)(g_xa + (size_t)row * DADDR + i);
        a[i] = v.x; a[i + 1] = v.y; a[i + 2] = v.z; a[i + 3] = v.w;
    }
    const float* Us[3] = { U1, U2, U3 };
    const float inv_tau = 1.f / (1.0f + 1e-8f);
#pragma unroll 1
    for (int rt = 0; rt < 3; rt++) {
        const float* U = Us[rt];
        float z[NEXP];
#pragma unroll
        for (int e = 0; e < NEXP; e++) {
            float s = 0.f;
#pragma unroll
            for (int i = 0; i < DADDR; i++) s += a[i] * __ldg(U + e * DADDR + i);
            z[e] = s;
        }
        unsigned used = 0;
        int ei[KSEL]; float v[KSEL];
#pragma unroll
        for (int t = 0; t < KSEL; t++) {
            float best = -INFINITY; int bi = 0;
#pragma unroll
            for (int e = 0; e < NEXP; e++) {
                bool ok = (((used >> e) & 1u) == 0u) && (z[e] > best);
                if (ok) { best = z[e]; bi = e; }
            }
            used |= 1u << bi; ei[t] = bi; v[t] = best;
        }
        float m = v[0] * inv_tau;
        float s0 = expf(v[0] * inv_tau - m);
        float s1 = expf(v[1] * inv_tau - m);
        float s2 = expf(v[2] * inv_tau - m);
        float inv = 1.f / (s0 + s1 + s2);
        float w[KSEL] = { s0 * inv, s1 * inv, s2 * inv };
        if (rt == 0) {
#pragma unroll
            for (int t = 0; t < KSEL; t++) {
                int p = atomicAdd(&g_cnt1[ei[t]], 1);
                g_rows1[ei[t] * NROWS + p] = row;
                g_wts1 [ei[t] * NROWS + p] = w[t];
                g_pos1[row * 3 + t] = (ei[t] << 16) | p;
            }
        } else if (rt == 1) {
#pragma unroll
            for (int t = 0; t < KSEL; t++) {
                int p = atomicAdd(&g_cnt2[ei[t]], 1);
                g_rows2[ei[t] * NROWS + p] = row;
                g_wts2 [ei[t] * NROWS + p] = w[t];
                g_pos2[row * 3 + t] = (ei[t] << 16) | p;
            }
        } else {
#pragma unroll
            for (int t = 0; t < KSEL; t++) {
                g_r3e[row * 3 + t] = ei[t];
                g_r3w[row * 3 + t] = w[t];
            }
        }
    }
}

// ---------------- grouped sparse GEMM (fp16 wmma, fp32 accum) -------------------
// 128 threads, 4 warps, block tile 128x128, warp tile 64x64, BK=32, 4-stage ring,
// ONE __syncthreads + ONE wait per TWO k-chunks; batched strip epilogue.
// pass 0: sloth[off1[e]+m] = w * (g_xh[rows1] @ W1[e]^T)
// pass 1: sloth[off2[e]+m] = w * (g_hh[rows2] @ W2[e]^T)
__global__ __launch_bounds__(128, 2) void k_gemm(int pass) {
    extern __shared__ __half sbuf[];       // NSTG x [A 5120 | B 5120] halves
    __shared__ int   rs[128];
    __shared__ float ws[128];

    const __half* A    = pass ? g_hh    : g_xh;
    const __half* W    = pass ? g_w2h   : g_w1h;
    const int*   rows  = pass ? g_rows2 : g_rows1;
    const float* wts   = pass ? g_wts2  : g_wts1;
    const int*   cnts  = pass ? g_cnt2  : g_cnt1;
    const int*   offs  = pass ? g_off2  : g_off1;

    int tid = threadIdx.x;
    int e, t = blockIdx.x, cnt_e = 0;
#pragma unroll 1
    for (e = 0; e < NEXP; e++) {
        cnt_e = cnts[e];
        int nt = (cnt_e + 127) >> 7;
        if (t < nt) break;
        t -= nt;
    }
    if (e >= NEXP) return;
    int m0 = t << 7;
    int c0 = blockIdx.y << 7;
    int base = offs[e];

    {
        int m = m0 + tid;
        bool ok = m < cnt_e;
        rs[tid] = ok ? rows[e * NROWS + m] : -1;
        ws[tid] = ok ? wts [e * NROWS + m] : 0.f;
    }
    __syncthreads();

    const __half* Wb = W + (size_t)e * (DIN * DIN) + (size_t)c0 * DIN;

    auto load_stage = [&](int kt, int s) {
        int k0 = kt * 32;
        __half* As = sbuf + s * STG_HALVES;
        __half* Bs = As + 128 * BKH;
#pragma unroll
        for (int i = tid; i < 512; i += 128) {
            int r = i >> 2, seg = i & 3;
            int gr = rs[r];
            int sz = (gr >= 0) ? 16 : 0;
            const __half* src = A + (size_t)(gr >= 0 ? gr : 0) * DIN + k0 + seg * 8;
            unsigned dst = (unsigned)__cvta_generic_to_shared(As + r * BKH + seg * 8);
            CP16(dst, src, sz);
        }
#pragma unroll
        for (int i = tid; i < 512; i += 128) {
            int n = i >> 2, seg = i & 3;
            const __half* src = Wb + (size_t)n * DIN + k0 + seg * 8;
            unsigned dst = (unsigned)__cvta_generic_to_shared(Bs + n * BKH + seg * 8);
            CP16F(dst, src);
        }
        CP_COMMIT();
    };

    int wid = tid >> 5, lane = tid & 31;
    int wm = wid & 1;   // row half: 64 rows
    int wn = wid >> 1;  // col half: 64 cols

    wmma::fragment<wmma::accumulator, 16, 16, 16, float> acc[4][4];
#pragma unroll
    for (int i = 0; i < 4; i++)
#pragma unroll
        for (int j = 0; j < 4; j++) wmma::fill_fragment(acc[i][j], 0.f);

    // compute one k-chunk from stage s
    auto compute_stage = [&](int s) {
        const __half* As = sbuf + s * STG_HALVES;
        const __half* Bs = As + 128 * BKH;
#pragma unroll
        for (int ks = 0; ks < 2; ks++) {
            wmma::fragment<wmma::matrix_a, 16, 16, 16, __half, wmma::row_major> af[4];
#pragma unroll
            for (int i = 0; i < 4; i++)
                wmma::load_matrix_sync(af[i], As + (wm * 64 + i * 16) * BKH + ks * 16, BKH);
#pragma unroll
            for (int j = 0; j < 4; j++) {
                wmma::fragment<wmma::matrix_b, 16, 16, 16, __half, wmma::col_major> bf;
                wmma::load_matrix_sync(bf, Bs + (wn * 64 + j * 16) * BKH + ks * 16, BKH);
#pragma unroll
                for (int i = 0; i < 4; i++)
                    wmma::mma_sync(acc[i][j], af[i], bf, acc[i][j]);
            }
        }
    };

    const int NK = DIN / 32;   // 32, even
    load_stage(0, 0);
    load_stage(1, 1);
    load_stage(2, 2);
    load_stage(3, 3);

#pragma unroll 1
    for (int kt = 0; kt < NK; kt += 2) {
        __syncthreads();   // all warps done with chunks kt-2, kt-1 (stage reuse safe)
        if (kt + 2 < NK) {
            load_stage(kt + 2, (kt + 2) & 3);
            load_stage(kt + 3, (kt + 3) & 3);
            CP_WAIT2();    // chunks kt, kt+1 landed (<=2 groups outstanding)
        } else {
            CP_WAIT0();
        }
        compute_stage(kt & 3);
        compute_stage((kt + 1) & 3);
    }

    __syncthreads();       // all MMAs done before reusing sbuf as fp32 staging

    // epilogue: per row-group, stage 16x64 fp32 strip, then scale+pack+store
    float* strip = (float*)sbuf + wid * (16 * EPLD);   // 4 warps x 4352B = 17408B
#pragma unroll
    for (int i = 0; i < 4; i++) {
        int rloc = wm * 64 + i * 16;
#pragma unroll
        for (int j = 0; j < 4; j++)
            wmma::store_matrix_sync(strip + j * 16, acc[i][j], EPLD, wmma::mem_row_major);
        __syncwarp();
        int r = lane >> 1;
        int ch = (lane & 1) * 32;
        int rr = rloc + r;
        if (rs[rr] >= 0) {
            float w = ws[rr];
            union { __half2 h2[16]; uint4 u[4]; } pk;
#pragma unroll
            for (int q = 0; q < 8; q++) {
                float4 v = *(const float4*)(strip + r * EPLD + ch + q * 4);
                pk.h2[q * 2]     = __floats2half2_rn(v.x * w, v.y * w);
                pk.h2[q * 2 + 1] = __floats2half2_rn(v.z * w, v.w * w);
            }
            __half* dst = g_sloth + (size_t)(base + m0 + rr) * DIN + c0 + wn * 64 + ch;
#pragma unroll
            for (int q = 0; q < 4; q++)
                *(uint4*)(dst + q * 8) = pk.u[q];
        }
        __syncwarp();
    }
}

// ---------------- combine 1: h = sum slots, gelu, -> fp16 ----------------
__global__ __launch_bounds__(256) void k_combine1() {
    int row = blockIdx.x;
    int c = threadIdx.x * 4;
    float4 acc = make_float4(0.f, 0.f, 0.f, 0.f);
#pragma unroll
    for (int q = 0; q < 3; q++) {
        int pv = g_pos1[row * 3 + q];
        int e = pv >> 16, p = pv & 0xFFFF;
        union { uint2 u; __half2 h2[2]; } v;
        v.u = *(const uint2*)(g_sloth + (size_t)(g_off1[e] + p) * DIN + c);
        float2 a = __half22float2(v.h2[0]);
        float2 b = __half22float2(v.h2[1]);
        acc.x += a.x; acc.y += a.y; acc.z += b.x; acc.w += b.y;
    }
    acc.x = gelu_exact(acc.x); acc.y = gelu_exact(acc.y);
    acc.z = gelu_exact(acc.z); acc.w = gelu_exact(acc.w);
    union { __half2 h2[2]; uint2 u; } pk;
    pk.h2[0] = __floats2half2_rn(acc.x, acc.y);
    pk.h2[1] = __floats2half2_rn(acc.z, acc.w);
    *(uint2*)(g_hh + (size_t)row * DIN + c) = pk.u;
}

// ---------------- combine 2: out = sum slots + routed bias ----------------
__global__ __launch_bounds__(256) void k_combine2(const float* __restrict__ b2,
                                                  float* __restrict__ out) {
    int row = blockIdx.x;
    int c = threadIdx.x * 4;
    float4 acc = make_float4(0.f, 0.f, 0.f, 0.f);
#pragma unroll
    for (int q = 0; q < 3; q++) {
        int pv = g_pos2[row * 3 + q];
        int e = pv >> 16, p = pv & 0xFFFF;
        union { uint2 u; __half2 h2[2]; } v;
        v.u = *(const uint2*)(g_sloth + (size_t)(g_off2[e] + p) * DIN + c);
        float2 a = __half22float2(v.h2[0]);
        float2 b = __half22float2(v.h2[1]);
        acc.x += a.x; acc.y += a.y; acc.z += b.x; acc.w += b.y;
    }
#pragma unroll
    for (int q = 0; q < 3; q++) {
        int e = g_r3e[row * 3 + q];
        float w = g_r3w[row * 3 + q];
        float4 v = *(const float4*)(b2 + (size_t)e * DIN + c);
        acc.x += w * v.x; acc.y += w * v.y; acc.z += w * v.z; acc.w += w * v.w;
    }
    *(float4*)(out + (size_t)row * DIN + c) = acc;
}

// ---------------- launch ----------------
extern "C" void kernel_launch(void* const* d_in, const int* in_sizes, int n_in,
                              void* d_out, int out_size) {
    const float* x  = (const float*)d_in[0];
    const float* Pw = (const float*)d_in[1];
    const float* U1 = (const float*)d_in[2];
    const float* U2 = (const float*)d_in[3];
    const float* U3 = (const float*)d_in[4];
    const float* W1 = (const float*)d_in[5];
    const float* W2 = (const float*)d_in[6];
    const float* b2 = (const float*)d_in[7];
    float* out = (float*)d_out;

    cudaFuncSetAttribute(k_gemm, cudaFuncAttributeMaxDynamicSharedMemorySize, SMEM_DYN);

    k_zero_counts<<<1, 32>>>();
    k_conv_w<<<(NEXP * DIN * DIN / 8) / 256, 256>>>(W1, 0);
    k_conv_w<<<(NEXP * DIN * DIN / 8) / 256, 256>>>(W2, 1);
    k_xa2<<<NROWS / 128, 128>>>(x, Pw);
    k_route<<<NROWS / 256, 256>>>(U1, U2, U3);
    k_prefix<<<1, 32>>>();

    dim3 gg(KSEL * NROWS / 128 + NEXP, DIN / 128);
    k_gemm<<<gg, 128, SMEM_DYN>>>(0);
    k_combine1<<<NROWS, 256>>>();
    k_gemm<<<gg, 128, SMEM_DYN>>>(1);
    k_combine2<<<NROWS, 256>>>(b2, out);
}

// round 15
// speedup vs baseline: 1.0812x; 1.0812x over previous
#include <cuda_runtime.h>
#include <cuda_fp16.h>
#include <mma.h>

using namespace nvcuda;

#define NROWS 65536      // B*T = 8*8192
#define DIN   1024
#define DADDR 64
#define NEXP  12
#define KSEL  3
#define STLD  20         // epilogue stage ldm in floats (80B, wmma-legal)

// k_gemm geometry: BK=32, padded row 40 halves (80B), 3-stage ring
#define BKH   40
#define STG_HALVES (2 * 128 * BKH)       // A+B per stage = 10240 halves
#define NSTG  3
#define SMEM_DYN (NSTG * STG_HALVES * 2) // 61440 B -> 2 CTAs/SM

// k_xa2 geometry: BK=32, padded row 40 halves
#define XBK   40

// ---------------- static device scratch (no allocations) ----------------
__device__ __half g_xh [NROWS * DIN];
__device__ __half g_hh [NROWS * DIN];
__device__ __half g_w1h[NEXP * DIN * DIN];
__device__ __half g_w2h[NEXP * DIN * DIN];
__device__ __half g_sloth[(size_t)KSEL * NROWS * DIN];
__device__ float  g_xa [NROWS * DADDR];
__device__ int    g_cnt1[NEXP], g_cnt2[NEXP];
__device__ int    g_off1[NEXP], g_off2[NEXP];
__device__ int    g_rows1[NEXP * NROWS];
__device__ float  g_wts1 [NEXP * NROWS];
__device__ int    g_rows2[NEXP * NROWS];
__device__ float  g_wts2 [NEXP * NROWS];
__device__ int    g_pos1[NROWS * 3];
__device__ int    g_pos2[NROWS * 3];
__device__ int    g_r3e[NROWS * 3];
__device__ float  g_r3w[NROWS * 3];

// ---------------- helpers ----------------
__device__ __forceinline__ uint4 pack8h(float4 a, float4 b) {
    union { __half2 h2[4]; uint4 u; } p;
    p.h2[0] = __floats2half2_rn(a.x, a.y);
    p.h2[1] = __floats2half2_rn(a.z, a.w);
    p.h2[2] = __floats2half2_rn(b.x, b.y);
    p.h2[3] = __floats2half2_rn(b.z, b.w);
    return p.u;
}
__device__ __forceinline__ float gelu_exact(float v) {
    return 0.5f * v * (1.f + erff(v * 0.70710678118654752f));
}

#define CP16(dst_s32, src, sz) \
    asm volatile("cp.async.cg.shared.global [%0], [%1], 16, %2;\n" \
                 :: "r"(dst_s32), "l"(src), "r"(sz))
#define CP16F(dst_s32, src) \
    asm volatile("cp.async.cg.shared.global [%0], [%1], 16;\n" \
                 :: "r"(dst_s32), "l"(src))
#define CP_COMMIT() asm volatile("cp.async.commit_group;\n" ::)
#define CP_WAIT1()  asm volatile("cp.async.wait_group 1;\n" ::)
#define CP_WAIT0()  asm volatile("cp.async.wait_group 0;\n" ::)

// ---------------- tiny kernels ----------------
__global__ void k_zero_counts() {
    int t = threadIdx.x;
    if (t < NEXP) { g_cnt1[t] = 0; g_cnt2[t] = 0; }
}

__global__ void k_conv_w(const float* __restrict__ s, int which) {
    size_t i = ((size_t)blockIdx.x * blockDim.x + threadIdx.x) * 8;
    float4 a = *(const float4*)(s + i);
    float4 b = *(const float4*)(s + i + 4);
    __half* d = which ? g_w2h : g_w1h;
    *(uint4*)(d + i) = pack8h(a, b);
}

__global__ void k_prefix() {
    if (threadIdx.x == 0) {
        int s = 0;
        for (int e = 0; e < NEXP; e++) { g_off1[e] = s; s += g_cnt1[e]; }
        s = 0;
        for (int e = 0; e < NEXP; e++) { g_off2[e] = s; s += g_cnt2[e]; }
    }
}

// ---------------- routing stage A: split-fp16 tensor GEMM ----------------
// xa = x @ P_w^T via (x_hi + x_lo)(P_hi + P_lo)^T dropping lo*lo (err ~2^-22).
// Also writes g_xh = fp16(x) for GEMM pass 0 (x read exactly once).
__global__ __launch_bounds__(128) void k_xa2(const float* __restrict__ x,
                                             const float* __restrict__ P) {
    __shared__ __half Ah[128 * XBK], Al[128 * XBK];
    __shared__ __half Bh[DADDR * XBK], Bl[DADDR * XBK];
    int r0 = blockIdx.x * 128;
    int tid = threadIdx.x;
    int wid = tid >> 5;

    wmma::fragment<wmma::accumulator, 16, 16, 16, float> acc[2][4];
#pragma unroll
    for (int i = 0; i < 2; i++)
#pragma unroll
        for (int j = 0; j < 4; j++) wmma::fill_fragment(acc[i][j], 0.f);

#pragma unroll 1
    for (int k0 = 0; k0 < DIN; k0 += 32) {
        __syncthreads();
#pragma unroll
        for (int i = tid; i < 1024; i += 128) {
            int r = i >> 3, c4 = i & 7;
            float4 v = *(const float4*)(x + (size_t)(r0 + r) * DIN + k0 + c4 * 4);
            __half h0 = __float2half_rn(v.x), h1 = __float2half_rn(v.y);
            __half h2 = __float2half_rn(v.z), h3 = __float2half_rn(v.w);
            __half l0 = __float2half_rn(v.x - __half2float(h0));
            __half l1 = __float2half_rn(v.y - __half2float(h1));
            __half l2 = __float2half_rn(v.z - __half2float(h2));
            __half l3 = __float2half_rn(v.w - __half2float(h3));
            union { __half h[4]; uint2 u; } ph, pl;
            ph.h[0] = h0; ph.h[1] = h1; ph.h[2] = h2; ph.h[3] = h3;
            pl.h[0] = l0; pl.h[1] = l1; pl.h[2] = l2; pl.h[3] = l3;
            *(uint2*)(Ah + r * XBK + c4 * 4) = ph.u;
            *(uint2*)(Al + r * XBK + c4 * 4) = pl.u;
            *(uint2*)(g_xh + (size_t)(r0 + r) * DIN + k0 + c4 * 4) = ph.u;
        }
#pragma unroll
        for (int i = tid; i < 512; i += 128) {
            int a = i >> 3, c4 = i & 7;
            float4 v = *(const float4*)(P + (size_t)a * DIN + k0 + c4 * 4);
            __half h0 = __float2half_rn(v.x), h1 = __float2half_rn(v.y);
            __half h2 = __float2half_rn(v.z), h3 = __float2half_rn(v.w);
            __half l0 = __float2half_rn(v.x - __half2float(h0));
            __half l1 = __float2half_rn(v.y - __half2float(h1));
            __half l2 = __float2half_rn(v.z - __half2float(h2));
            __half l3 = __float2half_rn(v.w - __half2float(h3));
            union { __half h[4]; uint2 u; } ph, pl;
            ph.h[0] = h0; ph.h[1] = h1; ph.h[2] = h2; ph.h[3] = h3;
            pl.h[0] = l0; pl.h[1] = l1; pl.h[2] = l2; pl.h[3] = l3;
            *(uint2*)(Bh + a * XBK + c4 * 4) = ph.u;
            *(uint2*)(Bl + a * XBK + c4 * 4) = pl.u;
        }
        __syncthreads();
#pragma unroll
        for (int ks = 0; ks < 2; ks++) {
            wmma::fragment<wmma::matrix_a, 16, 16, 16, __half, wmma::row_major> afh[2], afl[2];
#pragma unroll
            for (int i = 0; i < 2; i++) {
                wmma::load_matrix_sync(afh[i], Ah + (wid * 32 + i * 16) * XBK + ks * 16, XBK);
                wmma::load_matrix_sync(afl[i], Al + (wid * 32 + i * 16) * XBK + ks * 16, XBK);
            }
#pragma unroll
            for (int j = 0; j < 4; j++) {
                wmma::fragment<wmma::matrix_b, 16, 16, 16, __half, wmma::col_major> bfh, bfl;
                wmma::load_matrix_sync(bfh, Bh + (j * 16) * XBK + ks * 16, XBK);
                wmma::load_matrix_sync(bfl, Bl + (j * 16) * XBK + ks * 16, XBK);
#pragma unroll
                for (int i = 0; i < 2; i++) {
                    wmma::mma_sync(acc[i][j], afh[i], bfh, acc[i][j]);
                    wmma::mma_sync(acc[i][j], afh[i], bfl, acc[i][j]);
                    wmma::mma_sync(acc[i][j], afl[i], bfh, acc[i][j]);
                }
            }
        }
    }
#pragma unroll
    for (int i = 0; i < 2; i++)
#pragma unroll
        for (int j = 0; j < 4; j++)
            wmma::store_matrix_sync(g_xa + (size_t)(r0 + wid * 32 + i * 16) * DADDR + j * 16,
                                    acc[i][j], DADDR, wmma::mem_row_major);
}

// ---------------- routing stage B: z, top-3, softmax, scatter ----------------
__global__ void k_route(const float* __restrict__ U1, const float* __restrict__ U2,
                        const float* __restrict__ U3) {
    int row = blockIdx.x * blockDim.x + threadIdx.x;
    float a[DADDR];
#pragma unroll
    for (int i = 0; i < DADDR; i += 4) {
        float4 v = *(const float4*)(g_xa + (size_t)row * DADDR + i);
        a[i] = v.x; a[i + 1] = v.y; a[i + 2] = v.z; a[i + 3] = v.w;
    }
    const float* Us[3] = { U1, U2, U3 };
    const float inv_tau = 1.f / (1.0f + 1e-8f);
#pragma unroll 1
    for (int rt = 0; rt < 3; rt++) {
        const float* U = Us[rt];
        float z[NEXP];
#pragma unroll
        for (int e = 0; e < NEXP; e++) {
            float s = 0.f;
#pragma unroll
            for (int i = 0; i < DADDR; i++) s += a[i] * __ldg(U + e * DADDR + i);
            z[e] = s;
        }
        unsigned used = 0;
        int ei[KSEL]; float v[KSEL];
#pragma unroll
        for (int t = 0; t < KSEL; t++) {
            float best = -INFINITY; int bi = 0;
#pragma unroll
            for (int e = 0; e < NEXP; e++) {
                bool ok = (((used >> e) & 1u) == 0u) && (z[e] > best);
                if (ok) { best = z[e]; bi = e; }
            }
            used |= 1u << bi; ei[t] = bi; v[t] = best;
        }
        float m = v[0] * inv_tau;
        float s0 = expf(v[0] * inv_tau - m);
        float s1 = expf(v[1] * inv_tau - m);
        float s2 = expf(v[2] * inv_tau - m);
        float inv = 1.f / (s0 + s1 + s2);
        float w[KSEL] = { s0 * inv, s1 * inv, s2 * inv };
        if (rt == 0) {
#pragma unroll
            for (int t = 0; t < KSEL; t++) {
                int p = atomicAdd(&g_cnt1[ei[t]], 1);
                g_rows1[ei[t] * NROWS + p] = row;
                g_wts1 [ei[t] * NROWS + p] = w[t];
                g_pos1[row * 3 + t] = (ei[t] << 16) | p;
            }
        } else if (rt == 1) {
#pragma unroll
            for (int t = 0; t < KSEL; t++) {
                int p = atomicAdd(&g_cnt2[ei[t]], 1);
                g_rows2[ei[t] * NROWS + p] = row;
                g_wts2 [ei[t] * NROWS + p] = w[t];
                g_pos2[row * 3 + t] = (ei[t] << 16) | p;
            }
        } else {
#pragma unroll
            for (int t = 0; t < KSEL; t++) {
                g_r3e[row * 3 + t] = ei[t];
                g_r3w[row * 3 + t] = w[t];
            }
        }
    }
}

// ---------------- grouped sparse GEMM (fp16 wmma, fp32 accum) -------------------
// 128 threads, 4 warps, block tile 128x128, warp tile 64x64, BK=32, 3-stage ring.
// GRID SWAPPED: blockIdx.x = col tile (8), blockIdx.y = expert tile (1548) so the
// 8 col-tiles sharing one gathered A slab are consecutive -> A served from L2.
// pass 0: sloth[off1[e]+m] = w * (g_xh[rows1] @ W1[e]^T)
// pass 1: sloth[off2[e]+m] = w * (g_hh[rows2] @ W2[e]^T)
__global__ __launch_bounds__(128, 2) void k_gemm(int pass) {
    extern __shared__ __half sbuf[];       // NSTG x [A 5120 | B 5120] halves
    __shared__ int   rs[128];
    __shared__ float ws[128];

    const __half* A    = pass ? g_hh    : g_xh;
    const __half* W    = pass ? g_w2h   : g_w1h;
    const int*   rows  = pass ? g_rows2 : g_rows1;
    const float* wts   = pass ? g_wts2  : g_wts1;
    const int*   cnts  = pass ? g_cnt2  : g_cnt1;
    const int*   offs  = pass ? g_off2  : g_off1;

    int tid = threadIdx.x;
    int e, t = blockIdx.y, cnt_e = 0;
#pragma unroll 1
    for (e = 0; e < NEXP; e++) {
        cnt_e = cnts[e];
        int nt = (cnt_e + 127) >> 7;
        if (t < nt) break;
        t -= nt;
    }
    if (e >= NEXP) return;
    int m0 = t << 7;
    int c0 = blockIdx.x << 7;
    int base = offs[e];

    {
        int m = m0 + tid;
        bool ok = m < cnt_e;
        rs[tid] = ok ? rows[e * NROWS + m] : -1;
        ws[tid] = ok ? wts [e * NROWS + m] : 0.f;
    }
    __syncthreads();

    const __half* Wb = W + (size_t)e * (DIN * DIN) + (size_t)c0 * DIN;

    auto load_stage = [&](int kt, int s) {
        int k0 = kt * 32;
        __half* As = sbuf + s * STG_HALVES;
        __half* Bs = As + 128 * BKH;
#pragma unroll
        for (int i = tid; i < 512; i += 128) {
            int r = i >> 2, seg = i & 3;
            int gr = rs[r];
            int sz = (gr >= 0) ? 16 : 0;
            const __half* src = A + (size_t)(gr >= 0 ? gr : 0) * DIN + k0 + seg * 8;
            unsigned dst = (unsigned)__cvta_generic_to_shared(As + r * BKH + seg * 8);
            CP16(dst, src, sz);
        }
#pragma unroll
        for (int i = tid; i < 512; i += 128) {
            int n = i >> 2, seg = i & 3;
            const __half* src = Wb + (size_t)n * DIN + k0 + seg * 8;
            unsigned dst = (unsigned)__cvta_generic_to_shared(Bs + n * BKH + seg * 8);
            CP16F(dst, src);
        }
        CP_COMMIT();
    };

    int wid = tid >> 5, lane = tid & 31;
    int wm = wid & 1;   // row half: 64 rows
    int wn = wid >> 1;  // col half: 64 cols

    wmma::fragment<wmma::accumulator, 16, 16, 16, float> acc[4][4];
#pragma unroll
    for (int i = 0; i < 4; i++)
#pragma unroll
        for (int j = 0; j < 4; j++) wmma::fill_fragment(acc[i][j], 0.f);

    const int NK = DIN / 32;
    load_stage(0, 0);
    load_stage(1, 1);

#pragma unroll 1
    for (int kt = 0; kt < NK; kt++) {
        if (kt + 1 < NK) { CP_WAIT1(); } else { CP_WAIT0(); }
        __syncthreads();   // stage kt ready; all warps done with stage kt-1
        if (kt + 2 < NK) load_stage(kt + 2, (kt + 2) % NSTG);

        const __half* As = sbuf + (kt % NSTG) * STG_HALVES;
        const __half* Bs = As + 128 * BKH;
#pragma unroll
        for (int ks = 0; ks < 2; ks++) {
            wmma::fragment<wmma::matrix_a, 16, 16, 16, __half, wmma::row_major> af[4];
#pragma unroll
            for (int i = 0; i < 4; i++)
                wmma::load_matrix_sync(af[i], As + (wm * 64 + i * 16) * BKH + ks * 16, BKH);
#pragma unroll
            for (int j = 0; j < 4; j++) {
                wmma::fragment<wmma::matrix_b, 16, 16, 16, __half, wmma::col_major> bf;
                wmma::load_matrix_sync(bf, Bs + (wn * 64 + j * 16) * BKH + ks * 16, BKH);
#pragma unroll
                for (int i = 0; i < 4; i++)
                    wmma::mma_sync(acc[i][j], af[i], bf, acc[i][j]);
            }
        }
    }

    __syncthreads();       // all MMAs done before reusing sbuf as fp32 staging

    float* stage = (float*)sbuf;           // 4 warps x 16 x STLD floats = 5120 B
    float* st = stage + wid * 16 * STLD;
#pragma unroll
    for (int i = 0; i < 4; i++) {
        int rloc = wm * 64 + i * 16;
#pragma unroll
        for (int j = 0; j < 4; j++) {
            wmma::store_matrix_sync(st, acc[i][j], STLD, wmma::mem_row_major);
            __syncwarp();
            int r = lane >> 1;
            int cb = (lane & 1) * 8;
            int rr = rloc + r;
            if (rs[rr] >= 0) {
                float w = ws[rr];
                union { __half2 h2[4]; uint4 u; } pk;
#pragma unroll
                for (int q = 0; q < 4; q++) {
                    float v0 = st[r * STLD + cb + q * 2]     * w;
                    float v1 = st[r * STLD + cb + q * 2 + 1] * w;
                    pk.h2[q] = __floats2half2_rn(v0, v1);
                }
                *(uint4*)(g_sloth + (size_t)(base + m0 + rr) * DIN
                          + c0 + wn * 64 + j * 16 + cb) = pk.u;
            }
            __syncwarp();
        }
    }
}

// ---------------- combine 1: h = sum slots, gelu, -> fp16 ----------------
__global__ __launch_bounds__(256) void k_combine1() {
    int row = blockIdx.x;
    int c = threadIdx.x * 4;
    float4 acc = make_float4(0.f, 0.f, 0.f, 0.f);
#pragma unroll
    for (int q = 0; q < 3; q++) {
        int pv = g_pos1[row * 3 + q];
        int e = pv >> 16, p = pv & 0xFFFF;
        union { uint2 u; __half2 h2[2]; } v;
        v.u = *(const uint2*)(g_sloth + (size_t)(g_off1[e] + p) * DIN + c);
        float2 a = __half22float2(v.h2[0]);
        float2 b = __half22float2(v.h2[1]);
        acc.x += a.x; acc.y += a.y; acc.z += b.x; acc.w += b.y;
    }
    acc.x = gelu_exact(acc.x); acc.y = gelu_exact(acc.y);
    acc.z = gelu_exact(acc.z); acc.w = gelu_exact(acc.w);
    union { __half2 h2[2]; uint2 u; } pk;
    pk.h2[0] = __floats2half2_rn(acc.x, acc.y);
    pk.h2[1] = __floats2half2_rn(acc.z, acc.w);
    *(uint2*)(g_hh + (size_t)row * DIN + c) = pk.u;
}

// ---------------- combine 2: out = sum slots + routed bias ----------------
__global__ __launch_bounds__(256) void k_combine2(const float* __restrict__ b2,
                                                  float* __restrict__ out) {
    int row = blockIdx.x;
    int c = threadIdx.x * 4;
    float4 acc = make_float4(0.f, 0.f, 0.f, 0.f);
#pragma unroll
    for (int q = 0; q < 3; q++) {
        int pv = g_pos2[row * 3 + q];
        int e = pv >> 16, p = pv & 0xFFFF;
        union { uint2 u; __half2 h2[2]; } v;
        v.u = *(const uint2*)(g_sloth + (size_t)(g_off2[e] + p) * DIN + c);
        float2 a = __half22float2(v.h2[0]);
        float2 b = __half22float2(v.h2[1]);
        acc.x += a.x; acc.y += a.y; acc.z += b.x; acc.w += b.y;
    }
#pragma unroll
    for (int q = 0; q < 3; q++) {
        int e = g_r3e[row * 3 + q];
        float w = g_r3w[row * 3 + q];
        float4 v = *(const float4*)(b2 + (size_t)e * DIN + c);
        acc.x += w * v.x; acc.y += w * v.y; acc.z += w * v.z; acc.w += w * v.w;
    }
    *(float4*)(out + (size_t)row * DIN + c) = acc;
}

// ---------------- launch ----------------
extern "C" void kernel_launch(void* const* d_in, const int* in_sizes, int n_in,
                              void* d_out, int out_size) {
    const float* x  = (const float*)d_in[0];
    const float* Pw = (const float*)d_in[1];
    const float* U1 = (const float*)d_in[2];
    const float* U2 = (const float*)d_in[3];
    const float* U3 = (const float*)d_in[4];
    const float* W1 = (const float*)d_in[5];
    const float* W2 = (const float*)d_in[6];
    const float* b2 = (const float*)d_in[7];
    float* out = (float*)d_out;

    cudaFuncSetAttribute(k_gemm, cudaFuncAttributeMaxDynamicSharedMemorySize, SMEM_DYN);

    k_zero_counts<<<1, 32>>>();
    k_conv_w<<<(NEXP * DIN * DIN / 8) / 256, 256>>>(W1, 0);
    k_conv_w<<<(NEXP * DIN * DIN / 8) / 256, 256>>>(W2, 1);
    k_xa2<<<NROWS / 128, 128>>>(x, Pw);
    k_route<<<NROWS / 256, 256>>>(U1, U2, U3);
    k_prefix<<<1, 32>>>();

    dim3 gg(DIN / 128, KSEL * NROWS / 128 + NEXP);   // x = col tiles, y = expert tiles
    k_gemm<<<gg, 128, SMEM_DYN>>>(0);
    k_combine1<<<NROWS, 256>>>();
    k_gemm<<<gg, 128, SMEM_DYN>>>(1);
    k_combine2<<<NROWS, 256>>>(b2, out);
}